// round 2
// baseline (speedup 1.0000x reference)
#include <cuda_runtime.h>
#include <cstdint>

#define Zdim 41
#define Ydim 1024
#define Xdim 1024
#define NVOX (Zdim * Ydim * Xdim)      // 42,991,616
#define NWORDS (NVOX / 32)             // 1,343,488 bitmap words
#define C_IN 32
#define C_OUT 64
#define KVOL 27
#define WELEMS (KVOL * C_IN * C_OUT)   // 55,296

// Dense index grid: g_grid[lin] = point index. NEVER cleared — validity is
// gated by g_bitmap, which is wiped (dense 5.4 MB memset) at the start of
// every launch. Stale grid entries are never consulted, so replays are
// deterministic.
__device__ int      g_grid[NVOX];
__device__ unsigned g_bitmap[NWORDS];
// Weights transposed to [k][cout][cin] so a lane reads its cin-row with LDG.128.
__device__ float    g_wT[WELEMS];

__global__ void clear_bitmap_kernel() {
    int i = blockIdx.x * blockDim.x + threadIdx.x;
    uint4 z4 = make_uint4(0, 0, 0, 0);
    if (i * 4 < NWORDS) ((uint4*)g_bitmap)[i] = z4;
}

__global__ void transpose_w_kernel(const float* __restrict__ w) {
    int i = blockIdx.x * blockDim.x + threadIdx.x;
    if (i >= WELEMS) return;
    int k = i / (C_IN * C_OUT);
    int r = i % (C_IN * C_OUT);
    int cin = r / C_OUT;
    int cout = r % C_OUT;
    g_wT[(size_t)k * (C_IN * C_OUT) + cout * C_IN + cin] = w[i];
}

__global__ void scatter_kernel(const int* __restrict__ idx, int n) {
    int i = blockIdx.x * blockDim.x + threadIdx.x;
    if (i >= n) return;
    int z = idx[i * 4 + 1];
    int y = idx[i * 4 + 2];
    int x = idx[i * 4 + 3];
    unsigned lin = (unsigned)z * (Ydim * Xdim) + (unsigned)y * Xdim + (unsigned)x;
    g_grid[lin] = i;
    atomicOr(&g_bitmap[lin >> 5], 1u << (lin & 31));
}

// One warp per output point. Lanes 0..26 probe the L2-resident occupancy
// bitmap; only confirmed hits fetch the point index from the big grid.
// Inner product: feature row staged in smem (LDS.128 broadcast), weights
// loaded as float4 from the transposed copy.
__global__ void __launch_bounds__(256) conv_kernel(
    const float* __restrict__ feat,
    const int*   __restrict__ idx,
    float* __restrict__ out,
    int n)
{
    __shared__ float sf[8][C_IN];

    int warp_global = (blockIdx.x * blockDim.x + threadIdx.x) >> 5;
    int lane = threadIdx.x & 31;
    int wslot = (threadIdx.x >> 5);
    if (warp_global >= n) return;
    int i = warp_global;

    int z = idx[i * 4 + 1];
    int y = idx[i * 4 + 2];
    int x = idx[i * 4 + 3];

    int nb = -1;
    if (lane < KVOL) {
        int dz = lane / 9 - 1;
        int dy = (lane / 3) % 3 - 1;
        int dx = lane % 3 - 1;
        int nz = z + dz, ny = y + dy, nx = x + dx;
        if ((unsigned)nz < Zdim && (unsigned)ny < Ydim && (unsigned)nx < Xdim) {
            unsigned lin = (unsigned)nz * (Ydim * Xdim) + (unsigned)ny * Xdim + (unsigned)nx;
            unsigned word = g_bitmap[lin >> 5];
            if ((word >> (lin & 31)) & 1u)
                nb = g_grid[lin];          // rare: ~1.18 lanes per warp
        }
    }

    unsigned act = __ballot_sync(0xffffffffu, nb >= 0);

    float acc0 = 0.0f, acc1 = 0.0f;

    while (act) {
        int k = __ffs(act) - 1;
        act &= act - 1;
        int j = __shfl_sync(0xffffffffu, nb, k);

        // Coalesced 128 B gather of the neighbor's feature row, staged in smem.
        sf[wslot][lane] = feat[(size_t)j * C_IN + lane];
        __syncwarp();

        const float4* fs = (const float4*)sf[wslot];
        const float4* wa = (const float4*)(g_wT + (size_t)k * (C_IN * C_OUT) + lane * C_IN);
        const float4* wb = (const float4*)(g_wT + (size_t)k * (C_IN * C_OUT) + (lane + 32) * C_IN);

        #pragma unroll
        for (int c4 = 0; c4 < C_IN / 4; ++c4) {
            float4 fv = fs[c4];
            float4 a  = wa[c4];
            float4 b  = wb[c4];
            acc0 += fv.x * a.x + fv.y * a.y + fv.z * a.z + fv.w * a.w;
            acc1 += fv.x * b.x + fv.y * b.y + fv.z * b.z + fv.w * b.w;
        }
        __syncwarp();   // protect sf before next iteration overwrites it
    }

    out[(size_t)i * C_OUT + lane]      = acc0;
    out[(size_t)i * C_OUT + lane + 32] = acc1;
}

extern "C" void kernel_launch(void* const* d_in, const int* in_sizes, int n_in,
                              void* d_out, int out_size) {
    const float* feat = (const float*)d_in[0];
    const int*   idx  = (const int*)d_in[1];
    const float* w    = (const float*)d_in[2];
    float* out = (float*)d_out;

    int n = in_sizes[0] / C_IN;

    // 1. wipe the occupancy bitmap (dense, ~5.4 MB)
    int clr_blocks = (NWORDS / 4 + 255) / 256;
    clear_bitmap_kernel<<<clr_blocks, 256>>>();

    // 2. transpose weights to [k][cout][cin]
    transpose_w_kernel<<<(WELEMS + 255) / 256, 256>>>(w);

    // 3. scatter point indices + set occupancy bits
    scatter_kernel<<<(n + 255) / 256, 256>>>(idx, n);

    // 4. gather-conv: one warp per point (8 points / 256-thread block)
    conv_kernel<<<(n + 7) / 8, 256>>>(feat, idx, out, n);
}

// round 3
// speedup vs baseline: 3.9645x; 3.9645x over previous
#include <cuda_runtime.h>
#include <cstdint>

#define Zdim 41
#define Ydim 1024
#define Xdim 1024
#define NVOX (Zdim * Ydim * Xdim)      // 42,991,616
#define NWORDS (NVOX / 32)             // 1,343,488 bitmap words
#define C_IN 32
#define C_OUT 64
#define KVOL 27
#define KCENTER 13
#define WPAD 36                        // smem row pad: 16B-aligned, conflict-free

// Dense index grid: g_grid[lin] = point index. NEVER cleared — validity is
// gated by g_bitmap (wiped each launch), so stale entries are never read.
__device__ int      g_grid[NVOX];
__device__ unsigned g_bitmap[NWORDS];

__global__ void clear_bitmap_kernel() {
    int i = blockIdx.x * blockDim.x + threadIdx.x;
    if (i * 4 < NWORDS) ((uint4*)g_bitmap)[i] = make_uint4(0, 0, 0, 0);
}

__global__ void scatter_kernel(const int* __restrict__ idx, int n) {
    int i = blockIdx.x * blockDim.x + threadIdx.x;
    if (i >= n) return;
    int4 v = ((const int4*)idx)[i];
    unsigned lin = (unsigned)v.y * (Ydim * Xdim) + (unsigned)v.z * Xdim + (unsigned)v.w;
    g_grid[lin] = i;
    atomicOr(&g_bitmap[lin >> 5], 1u << (lin & 31));
}

// One warp per point (warp-strided persistent grid).
// Center offset always hits self -> dense path with smem-transposed W13.
// Non-center offsets: bitmap probe (L2-resident), rare hits use coalesced
// global weight loads in the original [k][cin][cout] layout.
__global__ void __launch_bounds__(256) conv_kernel(
    const float* __restrict__ feat,
    const int*   __restrict__ idx,
    const float* __restrict__ w,
    float* __restrict__ out,
    int n)
{
    __shared__ float ws[C_OUT * WPAD];   // W13 transposed: ws[cout*WPAD + cin]
    __shared__ float sf[8][C_IN];        // per-warp feature staging

    // Load + transpose center weights once per block.
    for (int e = threadIdx.x; e < C_IN * C_OUT; e += blockDim.x) {
        int cin = e >> 6, cout = e & 63;
        ws[cout * WPAD + cin] = w[KCENTER * C_IN * C_OUT + e];
    }
    __syncthreads();

    int lane   = threadIdx.x & 31;
    int wslot  = threadIdx.x >> 5;
    int warp_g = (blockIdx.x * blockDim.x + threadIdx.x) >> 5;
    int nwarps = (gridDim.x * blockDim.x) >> 5;

    // Per-lane neighbor offset (lanes 0..26), center excluded from probing.
    int dz = lane / 9 - 1;
    int dy = (lane / 3) % 3 - 1;
    int dx = lane % 3 - 1;
    bool is_probe_lane = (lane < KVOL) && (lane != KCENTER);

    const float4* wsv = (const float4*)ws;

    for (int i = warp_g; i < n; i += nwarps) {
        int4 v = ((const int4*)idx)[i];   // broadcast load
        int z = v.y, y = v.z, x = v.w;

        // ---- probe non-center neighbors via L2-resident bitmap ----
        int nb = -1;
        if (is_probe_lane) {
            int nz = z + dz, ny = y + dy, nx = x + dx;
            if ((unsigned)nz < Zdim && (unsigned)ny < Ydim && (unsigned)nx < Xdim) {
                unsigned lin = (unsigned)nz * (Ydim * Xdim) + (unsigned)ny * Xdim + (unsigned)nx;
                unsigned word = g_bitmap[lin >> 5];
                if ((word >> (lin & 31)) & 1u)
                    nb = g_grid[lin];          // rare (~0.18 per point)
            }
        }
        unsigned act = __ballot_sync(0xffffffffu, nb >= 0);

        // ---- stage own feature row (also used by center path) ----
        sf[wslot][lane] = feat[(size_t)i * C_IN + lane];
        __syncwarp();

        // ---- center contribution: smem weights, LDS.128 both sides ----
        float acc0 = 0.0f, acc1 = 0.0f;
        {
            const float4* fs = (const float4*)sf[wslot];
            const float4* wa = (const float4*)(ws + lane * WPAD);
            const float4* wb = (const float4*)(ws + (lane + 32) * WPAD);
            #pragma unroll
            for (int c4 = 0; c4 < C_IN / 4; ++c4) {
                float4 fv = fs[c4];
                float4 a  = wsv[0], b;  // placate compiler; real loads below
                a = wa[c4]; b = wb[c4];
                acc0 += fv.x * a.x + fv.y * a.y + fv.z * a.z + fv.w * a.w;
                acc1 += fv.x * b.x + fv.y * b.y + fv.z * b.z + fv.w * b.w;
            }
        }
        __syncwarp();

        // ---- rare neighbor contributions: coalesced global weights ----
        while (act) {
            int k = __ffs(act) - 1;
            act &= act - 1;
            int j = __shfl_sync(0xffffffffu, nb, k);

            sf[wslot][lane] = feat[(size_t)j * C_IN + lane];
            __syncwarp();

            const float* wk = w + (size_t)k * C_IN * C_OUT;
            const float4* fs = (const float4*)sf[wslot];
            #pragma unroll
            for (int c4 = 0; c4 < C_IN / 4; ++c4) {
                float4 fv = fs[c4];
                #pragma unroll
                for (int q = 0; q < 4; ++q) {
                    float fvq = (q == 0) ? fv.x : (q == 1) ? fv.y : (q == 2) ? fv.z : fv.w;
                    int c = c4 * 4 + q;
                    acc0 += fvq * wk[c * C_OUT + lane];
                    acc1 += fvq * wk[c * C_OUT + lane + 32];
                }
            }
            __syncwarp();
        }

        out[(size_t)i * C_OUT + lane]      = acc0;
        out[(size_t)i * C_OUT + lane + 32] = acc1;
    }
}

extern "C" void kernel_launch(void* const* d_in, const int* in_sizes, int n_in,
                              void* d_out, int out_size) {
    const float* feat = (const float*)d_in[0];
    const int*   idx  = (const int*)d_in[1];
    const float* w    = (const float*)d_in[2];
    float* out = (float*)d_out;

    int n = in_sizes[0] / C_IN;

    clear_bitmap_kernel<<<(NWORDS / 4 + 255) / 256, 256>>>();
    scatter_kernel<<<(n + 255) / 256, 256>>>(idx, n);
    conv_kernel<<<1184, 256>>>(feat, idx, w, out, n);
}